// round 3
// baseline (speedup 1.0000x reference)
#include <cuda_runtime.h>
#include <math.h>

// Problem shape (fixed by the dataset)
#define B_    32
#define S_    2048
#define ENC_  1024
#define DEC_  512
#define WROW  (ENC_ + DEC_)      // 1536, row stride of W
#define M_TOTAL (B_ * S_)        // 65536

// GEMM tiling
#define BM 128
#define BN 128
#define BK 16
// 256 threads = 16x16 thread grid, 8x8 micro-tile per thread

// Scratch (no allocations allowed): hproj and partial score planes
__device__ float g_hproj[B_ * DEC_];                    // 64 KB
__device__ float g_partial[(DEC_ / BN) * M_TOTAL];      // 4 * 65536 floats = 1 MB

// ---------------------------------------------------------------------------
// Kernel 1: h_proj[b][n] = bias[n] + sum_k hidden[b][k] * W[n][k]   (Wh part)
// ---------------------------------------------------------------------------
__global__ void hproj_kernel(const float* __restrict__ hidden,
                             const float* __restrict__ W,
                             const float* __restrict__ bvec) {
    __shared__ float hid[DEC_];
    const int b = blockIdx.x;
    const int n = threadIdx.x;           // 0..511
    hid[n] = hidden[b * DEC_ + n];
    __syncthreads();

    const float4* wrow = reinterpret_cast<const float4*>(W + (size_t)n * WROW);
    float acc = bvec[n];
#pragma unroll 8
    for (int k4 = 0; k4 < DEC_ / 4; k4++) {
        float4 w = wrow[k4];
        acc += hid[k4 * 4 + 0] * w.x;
        acc += hid[k4 * 4 + 1] * w.y;
        acc += hid[k4 * 4 + 2] * w.z;
        acc += hid[k4 * 4 + 3] * w.w;
    }
    g_hproj[b * DEC_ + n] = acc;
}

// ---------------------------------------------------------------------------
// Kernel 2: fused GEMM + tanh + v-dot partial reduction.
//   C[m][d] = sum_e enc[m][e] * We[d][e],  We[d][e] = W[d][DEC_ + e]
//   partial[nt][m] = sum_{d in tile nt} v[d] * tanh(C[m][d] + hproj[b(m)][d])
// Block = 128 (m) x 128 (d) tile, K loop over 1024 in steps of 16.
// ---------------------------------------------------------------------------
__global__ __launch_bounds__(256, 2)
void score_kernel(const float* __restrict__ enc,
                  const float* __restrict__ W,
                  const float* __restrict__ v) {
    __shared__ float As[BK][BM + 4];
    __shared__ float Bs[BK][BN + 4];
    __shared__ float red[16][BM];

    const int tid = threadIdx.x;
    const int tx  = tid & 15;
    const int ty  = tid >> 4;
    const int bm  = blockIdx.y * BM;     // row (b,s) offset; never spans batches
    const int bn  = blockIdx.x * BN;     // d offset
    const int batch = bm / S_;

    const float* Aptr = enc + (size_t)bm * ENC_;
    const float* Bptr = W + (size_t)bn * WROW + DEC_;   // We rows, stride WROW

    float acc[8][8];
#pragma unroll
    for (int i = 0; i < 8; i++)
#pragma unroll
        for (int j = 0; j < 8; j++) acc[i][j] = 0.f;

    for (int kt = 0; kt < ENC_; kt += BK) {
        // Load A and B tiles, transposed into smem (k-major)
#pragma unroll
        for (int l = 0; l < 2; l++) {
            int f   = tid + l * 256;        // 0..511
            int row = f >> 2;               // 0..127
            int kq  = (f & 3) << 2;         // 0,4,8,12
            float4 a = *reinterpret_cast<const float4*>(Aptr + (size_t)row * ENC_ + kt + kq);
            As[kq + 0][row] = a.x; As[kq + 1][row] = a.y;
            As[kq + 2][row] = a.z; As[kq + 3][row] = a.w;
            float4 bb = *reinterpret_cast<const float4*>(Bptr + (size_t)row * WROW + kt + kq);
            Bs[kq + 0][row] = bb.x; Bs[kq + 1][row] = bb.y;
            Bs[kq + 2][row] = bb.z; Bs[kq + 3][row] = bb.w;
        }
        __syncthreads();

#pragma unroll
        for (int kk = 0; kk < BK; kk++) {
            float4 a0 = *reinterpret_cast<const float4*>(&As[kk][ty * 8]);
            float4 a1 = *reinterpret_cast<const float4*>(&As[kk][ty * 8 + 4]);
            float4 b0 = *reinterpret_cast<const float4*>(&Bs[kk][tx * 8]);
            float4 b1 = *reinterpret_cast<const float4*>(&Bs[kk][tx * 8 + 4]);
            float af[8] = {a0.x, a0.y, a0.z, a0.w, a1.x, a1.y, a1.z, a1.w};
            float bf[8] = {b0.x, b0.y, b0.z, b0.w, b1.x, b1.y, b1.z, b1.w};
#pragma unroll
            for (int i = 0; i < 8; i++)
#pragma unroll
                for (int j = 0; j < 8; j++)
                    acc[i][j] += af[i] * bf[j];
        }
        __syncthreads();
    }

    // Epilogue: + hproj, tanh, * v, reduce over this block's 128 d-columns.
    float vv[8], hh[8];
#pragma unroll
    for (int j = 0; j < 8; j++) {
        int d = bn + tx * 8 + j;
        vv[j] = v[d];
        hh[j] = g_hproj[batch * DEC_ + d];
    }
    float p[8];
#pragma unroll
    for (int i = 0; i < 8; i++) {
        float s = 0.f;
#pragma unroll
        for (int j = 0; j < 8; j++)
            s += vv[j] * tanhf(acc[i][j] + hh[j]);
        p[i] = s;
    }
#pragma unroll
    for (int i = 0; i < 8; i++)
        red[tx][ty * 8 + i] = p[i];
    __syncthreads();

    if (tid < BM) {
        float s = 0.f;
#pragma unroll
        for (int t = 0; t < 16; t++) s += red[t][tid];
        g_partial[(size_t)blockIdx.x * M_TOTAL + bm + tid] = s;
    }
}

// ---------------------------------------------------------------------------
// Kernel 3: sum the 4 partial planes, softmax over S per batch.
// ---------------------------------------------------------------------------
__global__ void softmax_kernel(float* __restrict__ out) {
    __shared__ float sc[S_];
    __shared__ float redbuf[256];
    const int b   = blockIdx.x;
    const int tid = threadIdx.x;

    float lmax = -1e30f;
    for (int s0 = tid; s0 < S_; s0 += 256) {
        float sum = 0.f;
#pragma unroll
        for (int n = 0; n < DEC_ / BN; n++)
            sum += g_partial[(size_t)n * M_TOTAL + b * S_ + s0];
        sc[s0] = sum;
        lmax = fmaxf(lmax, sum);
    }
    redbuf[tid] = lmax;
    __syncthreads();
    for (int off = 128; off > 0; off >>= 1) {
        if (tid < off) redbuf[tid] = fmaxf(redbuf[tid], redbuf[tid + off]);
        __syncthreads();
    }
    const float m = redbuf[0];
    __syncthreads();

    float lsum = 0.f;
    for (int s0 = tid; s0 < S_; s0 += 256) {
        float e = expf(sc[s0] - m);
        sc[s0] = e;
        lsum += e;
    }
    redbuf[tid] = lsum;
    __syncthreads();
    for (int off = 128; off > 0; off >>= 1) {
        if (tid < off) redbuf[tid] += redbuf[tid + off];
        __syncthreads();
    }
    const float inv = 1.f / redbuf[0];
    __syncthreads();

    for (int s0 = tid; s0 < S_; s0 += 256)
        out[b * S_ + s0] = sc[s0] * inv;
}

// ---------------------------------------------------------------------------
extern "C" void kernel_launch(void* const* d_in, const int* in_sizes, int n_in,
                              void* d_out, int out_size) {
    const float* hidden = (const float*)d_in[0];   // (32, 512)
    const float* enc    = (const float*)d_in[1];   // (32, 2048, 1024)
    const float* W      = (const float*)d_in[2];   // (512, 1536)
    const float* bvec   = (const float*)d_in[3];   // (512,)
    const float* v      = (const float*)d_in[4];   // (512,)
    float* out          = (float*)d_out;           // (32, 1, 2048)

    hproj_kernel<<<B_, DEC_>>>(hidden, W, bvec);

    dim3 grid(DEC_ / BN, M_TOTAL / BM);            // (4, 512)
    score_kernel<<<grid, 256>>>(enc, W, v);

    softmax_kernel<<<B_, 256>>>(out);
}

// round 5
// speedup vs baseline: 2.0328x; 2.0328x over previous
#include <cuda_runtime.h>
#include <cuda_bf16.h>
#include <cstdint>
#include <math.h>

#define B_      32
#define S_      2048
#define ENC_    1024
#define DEC_    512
#define WROW    1536
#define M_TOTAL 65536

#define BM 128
#define BN 256
#define KC 64
#define NSTAGE 16
#define NTHREADS 512

// dynamic smem layout (from 1024-aligned base)
#define OFF_VS    0
#define OFF_HS    1024
#define OFF_RED   2048
#define OFF_TILES 4096
#define STAGE_BYTES 98304
#define AHI_OFF(s) (OFF_TILES + (s) * STAGE_BYTES)
#define ALO_OFF(s) (AHI_OFF(s) + 16384)
#define BHI_OFF(s) (AHI_OFF(s) + 32768)
#define BLO_OFF(s) (AHI_OFF(s) + 65536)
#define SMEM_DYN (1024 + OFF_TILES + 2 * STAGE_BYTES)   // 201728

__device__ __align__(256) __nv_bfloat16 g_we_hi[DEC_ * ENC_];
__device__ __align__(256) __nv_bfloat16 g_we_lo[DEC_ * ENC_];
__device__ float g_hproj[B_ * DEC_];
__device__ float g_partial[2 * M_TOTAL];

// ---------------- helpers ----------------
__device__ __forceinline__ uint32_t smem_u32(const void* p) {
    uint32_t a;
    asm("{ .reg .u64 t; cvta.to.shared.u64 t, %1; cvt.u32.u64 %0, t; }" : "=r"(a) : "l"(p));
    return a;
}
__device__ __forceinline__ uint32_t swz(uint32_t o) { return o ^ ((o >> 3) & 0x70); }
__device__ __forceinline__ void cp16(uint32_t dst, const void* src) {
    asm volatile("cp.async.cg.shared.global [%0], [%1], 16;"
                 :: "r"(dst), "l"(__cvta_generic_to_global(src)) : "memory");
}
__device__ __forceinline__ uint32_t pk(__nv_bfloat16 a, __nv_bfloat16 b) {
    __nv_bfloat162 p; p.x = a; p.y = b;
    return *reinterpret_cast<uint32_t*>(&p);
}
__device__ __forceinline__ float ftanh(float x) {
    float e = __expf(2.f * x);
    return 1.f - __fdividef(2.f, e + 1.f);
}
__device__ __forceinline__ void ldsm4(uint32_t* r, uint32_t addr) {
    asm volatile("ldmatrix.sync.aligned.m8n8.x4.shared.b16 {%0,%1,%2,%3}, [%4];"
                 : "=r"(r[0]), "=r"(r[1]), "=r"(r[2]), "=r"(r[3]) : "r"(addr));
}
__device__ __forceinline__ void mma16816(float* c, const uint32_t* a, uint32_t b0, uint32_t b1) {
    asm volatile("mma.sync.aligned.m16n8k16.row.col.f32.bf16.bf16.f32 "
                 "{%0,%1,%2,%3}, {%4,%5,%6,%7}, {%8,%9}, {%0,%1,%2,%3};"
                 : "+f"(c[0]), "+f"(c[1]), "+f"(c[2]), "+f"(c[3])
                 : "r"(a[0]), "r"(a[1]), "r"(a[2]), "r"(a[3]), "r"(b0), "r"(b1));
}

// ---------------- kernel 0: We -> bf16 hi/lo ----------------
__global__ void conv_we_kernel(const float* __restrict__ W) {
    const int d = blockIdx.x, t = threadIdx.x;
    float4 x = *reinterpret_cast<const float4*>(W + (size_t)d * WROW + DEC_ + t * 4);
    float e[4] = {x.x, x.y, x.z, x.w};
    __nv_bfloat16 h[4], l[4];
#pragma unroll
    for (int i = 0; i < 4; i++) {
        h[i] = __float2bfloat16(e[i]);
        l[i] = __float2bfloat16(e[i] - __bfloat162float(h[i]));
    }
    *reinterpret_cast<uint2*>(g_we_hi + d * ENC_ + t * 4) = make_uint2(pk(h[0],h[1]), pk(h[2],h[3]));
    *reinterpret_cast<uint2*>(g_we_lo + d * ENC_ + t * 4) = make_uint2(pk(l[0],l[1]), pk(l[2],l[3]));
}

// ---------------- kernel 1: hproj ----------------
__global__ void hproj_kernel(const float* __restrict__ hidden,
                             const float* __restrict__ W,
                             const float* __restrict__ bvec) {
    __shared__ float hid[DEC_];
    const int b = blockIdx.y;
    const int n = blockIdx.x * 128 + threadIdx.x;
    for (int i = threadIdx.x; i < DEC_; i += 128) hid[i] = hidden[b * DEC_ + i];
    __syncthreads();
    const float4* wr = reinterpret_cast<const float4*>(W + (size_t)n * WROW);
    float acc = bvec[n];
#pragma unroll 8
    for (int k = 0; k < DEC_ / 4; k++) {
        float4 w = wr[k];
        acc += hid[k*4]*w.x + hid[k*4+1]*w.y + hid[k*4+2]*w.z + hid[k*4+3]*w.w;
    }
    g_hproj[b * DEC_ + n] = acc;
}

// ---------------- kernel 2: HMMA GEMM + fused epilogue ----------------
__global__ __launch_bounds__(NTHREADS, 1)
void gemm_kernel(const float* __restrict__ enc, const float* __restrict__ v) {
    extern __shared__ char sraw[];
    uint32_t sb0 = smem_u32(sraw);
    uint32_t sb = (sb0 + 1023u) & ~1023u;
    char* smem = sraw + (sb - sb0);

    const int tid  = threadIdx.x;
    const int lane = tid & 31;
    const int w    = tid >> 5;          // 0..15
    const int wm   = w >> 2;            // 0..3  (M: 32 rows each)
    const int wn   = w & 3;             // 0..3  (N: 64 cols each)
    const int g8   = lane >> 3;         // ldmatrix group
    const int r8   = lane & 7;
    const int n0   = blockIdx.x * BN;
    const int m0   = blockIdx.y * BM;
    const int batch = m0 >> 11;

    float* vs = (float*)(smem + OFF_VS);
    float* hs = (float*)(smem + OFF_HS);
    if (tid < 256) {
        vs[tid] = v[n0 + tid];
        hs[tid] = g_hproj[batch * DEC_ + n0 + tid];
    }

    // A load assignment: row = tid>>2 (0..127), 16 floats starting at (tid&3)*16
    const int arow = tid >> 2;
    const int acol = (tid & 3) * 16;
    const float* aptr = enc + (size_t)(m0 + arow) * ENC_ + acol;

    // B cp.async assignment: 4 iters of (row, chunk)
    // prologue: B(0) + A(0)
    {
        uint32_t bh = sb + BHI_OFF(0), bl = sb + BLO_OFF(0);
#pragma unroll
        for (int i = 0; i < 4; i++) {
            int id = tid + i * NTHREADS, row = id >> 3, c = id & 7;
            uint32_t so = swz(row * 128 + c * 16);
            int g = (n0 + row) * ENC_ + c * 8;
            cp16(bh + so, g_we_hi + g);
            cp16(bl + so, g_we_lo + g);
        }
        asm volatile("cp.async.commit_group;" ::: "memory");
    }
    float4 areg[4];
#pragma unroll
    for (int j = 0; j < 4; j++) areg[j] = *reinterpret_cast<const float4*>(aptr + j * 4);

    float c[2][8][4];
#pragma unroll
    for (int mt = 0; mt < 2; mt++)
#pragma unroll
        for (int nt = 0; nt < 8; nt++)
#pragma unroll
            for (int q = 0; q < 4; q++) c[mt][nt][q] = 0.f;

    // precomputed ldmatrix base offsets (row part) for this thread
    const int a_row_sel = r8 + (g8 & 1) * 8;            // 0..15 within m16 tile
    const int chunk16   = (g8 >> 1) * 16;               // 0 or 16 bytes

#pragma unroll 1
    for (int kt = 0; kt < NSTAGE; kt++) {
        const int b = kt & 1;
        asm volatile("cp.async.wait_group 0;" ::: "memory");

        // convert A regs -> bf16 hi/lo swizzled SMEM
        {
            char* ah = smem + AHI_OFF(b);
            char* al = smem + ALO_OFF(b);
#pragma unroll
            for (int j = 0; j < 4; j++) {
                float e0=areg[j].x, e1=areg[j].y, e2=areg[j].z, e3=areg[j].w;
                __nv_bfloat16 h0=__float2bfloat16(e0), h1=__float2bfloat16(e1);
                __nv_bfloat16 h2=__float2bfloat16(e2), h3=__float2bfloat16(e3);
                __nv_bfloat16 l0=__float2bfloat16(e0-__bfloat162float(h0));
                __nv_bfloat16 l1=__float2bfloat16(e1-__bfloat162float(h1));
                __nv_bfloat16 l2=__float2bfloat16(e2-__bfloat162float(h2));
                __nv_bfloat16 l3=__float2bfloat16(e3-__bfloat162float(h3));
                uint32_t off = swz(arow * 128 + (acol + j * 4) * 2);
                *reinterpret_cast<uint2*>(ah + off) = make_uint2(pk(h0,h1), pk(h2,h3));
                *reinterpret_cast<uint2*>(al + off) = make_uint2(pk(l0,l1), pk(l2,l3));
            }
        }
        __syncthreads();

        // prefetch next stage
        if (kt + 1 < NSTAGE) {
            const int nb = (kt + 1) & 1;
            const int kb = (kt + 1) * KC;
            uint32_t bh = sb + BHI_OFF(nb), bl = sb + BLO_OFF(nb);
#pragma unroll
            for (int i = 0; i < 4; i++) {
                int id = tid + i * NTHREADS, row = id >> 3, cc = id & 7;
                uint32_t so = swz(row * 128 + cc * 16);
                int g = (n0 + row) * ENC_ + kb + cc * 8;
                cp16(bh + so, g_we_hi + g);
                cp16(bl + so, g_we_lo + g);
            }
            asm volatile("cp.async.commit_group;" ::: "memory");
#pragma unroll
            for (int j = 0; j < 4; j++)
                areg[j] = *reinterpret_cast<const float4*>(aptr + kb + j * 4);
        }

        // compute this stage: 4 k16 steps
        const uint32_t ahb = sb + AHI_OFF(b), alb = sb + ALO_OFF(b);
        const uint32_t bhb = sb + BHI_OFF(b), blb = sb + BLO_OFF(b);
#pragma unroll
        for (int k16 = 0; k16 < 4; k16++) {
            const uint32_t kby = k16 * 32 + chunk16;
            uint32_t ah[2][4], al[2][4], bh[4][4], bl[4][4];
#pragma unroll
            for (int mt = 0; mt < 2; mt++) {
                uint32_t ro = swz((wm * 32 + mt * 16 + a_row_sel) * 128 + kby);
                ldsm4(ah[mt], ahb + ro);
                ldsm4(al[mt], alb + ro);
            }
#pragma unroll
            for (int ng = 0; ng < 4; ng++) {
                uint32_t ro = swz((wn * 64 + ng * 16 + a_row_sel) * 128 + kby);
                ldsm4(bh[ng], bhb + ro);
                ldsm4(bl[ng], blb + ro);
            }
#pragma unroll
            for (int mt = 0; mt < 2; mt++)
#pragma unroll
                for (int ng = 0; ng < 4; ng++)
#pragma unroll
                    for (int s = 0; s < 2; s++) {
                        float* cc = c[mt][ng * 2 + s];
                        mma16816(cc, ah[mt], bh[ng][s], bh[ng][s + 2]);
                        mma16816(cc, ah[mt], bl[ng][s], bl[ng][s + 2]);
                        mma16816(cc, al[mt], bh[ng][s], bh[ng][s + 2]);
                    }
        }
        __syncthreads();
    }

    // ---- fused epilogue: v . tanh(C + h) , reduce over N ----
    const int g = lane >> 2, q = lane & 3;
    float* red = (float*)(smem + OFF_RED);
#pragma unroll
    for (int mt = 0; mt < 2; mt++) {
        float r0 = 0.f, r1 = 0.f;
#pragma unroll
        for (int nt = 0; nt < 8; nt++) {
            int n = wn * 64 + nt * 8 + q * 2;
            float v0 = vs[n], v1 = vs[n + 1], h0 = hs[n], h1 = hs[n + 1];
            r0 += v0 * ftanh(c[mt][nt][0] + h0) + v1 * ftanh(c[mt][nt][1] + h1);
            r1 += v0 * ftanh(c[mt][nt][2] + h0) + v1 * ftanh(c[mt][nt][3] + h1);
        }
#pragma unroll
        for (int msk = 1; msk <= 2; msk <<= 1) {
            r0 += __shfl_xor_sync(0xffffffff, r0, msk);
            r1 += __shfl_xor_sync(0xffffffff, r1, msk);
        }
        if (q == 0) {
            int row = wm * 32 + mt * 16 + g;
            red[row * 4 + wn] = r0;
            red[(row + 8) * 4 + wn] = r1;
        }
    }
    __syncthreads();
    if (tid < 128)
        g_partial[(size_t)blockIdx.x * M_TOTAL + m0 + tid] =
            red[tid * 4] + red[tid * 4 + 1] + red[tid * 4 + 2] + red[tid * 4 + 3];
}

// ---------------- kernel 3: softmax ----------------
__global__ void softmax_kernel(float* __restrict__ out) {
    __shared__ float sc[S_];
    __shared__ float rb[256];
    const int b = blockIdx.x, tid = threadIdx.x;
    float lmax = -1e30f;
    for (int s = tid; s < S_; s += 256) {
        float x = g_partial[b * S_ + s] + g_partial[M_TOTAL + b * S_ + s];
        sc[s] = x;
        lmax = fmaxf(lmax, x);
    }
    rb[tid] = lmax; __syncthreads();
    for (int o = 128; o > 0; o >>= 1) {
        if (tid < o) rb[tid] = fmaxf(rb[tid], rb[tid + o]);
        __syncthreads();
    }
    const float m = rb[0]; __syncthreads();
    float ls = 0.f;
    for (int s = tid; s < S_; s += 256) {
        float e = __expf(sc[s] - m);
        sc[s] = e; ls += e;
    }
    rb[tid] = ls; __syncthreads();
    for (int o = 128; o > 0; o >>= 1) {
        if (tid < o) rb[tid] += rb[tid + o];
        __syncthreads();
    }
    const float inv = 1.f / rb[0]; __syncthreads();
    for (int s = tid; s < S_; s += 256)
        out[b * S_ + s] = sc[s] * inv;
}

// ---------------- launcher ----------------
extern "C" void kernel_launch(void* const* d_in, const int* in_sizes, int n_in,
                              void* d_out, int out_size) {
    const float* hidden = (const float*)d_in[0];
    const float* enc    = (const float*)d_in[1];
    const float* W      = (const float*)d_in[2];
    const float* bvec   = (const float*)d_in[3];
    const float* v      = (const float*)d_in[4];
    float* out          = (float*)d_out;

    cudaFuncSetAttribute(gemm_kernel, cudaFuncAttributeMaxDynamicSharedMemorySize, SMEM_DYN);

    conv_we_kernel<<<DEC_, 256>>>(W);
    hproj_kernel<<<dim3(4, B_), 128>>>(hidden, W, bvec);
    gemm_kernel<<<dim3(DEC_ / BN, M_TOTAL / BM), NTHREADS, SMEM_DYN>>>(enc, v);
    softmax_kernel<<<B_, 256>>>(out);
}